// round 17
// baseline (speedup 1.0000x reference)
#include <cuda_runtime.h>
#include <cuda_fp16.h>
#include <cstdint>

#define NU   50000
#define NPR  20000
#define DU   128
#define Hdim 256
#define OUTD 128
#define NE   800000
#define NPAIR 200000

// ------------------------- scratch (device globals, no allocs) -------------
__device__ __half g_hu  [(size_t)NU  * Hdim];
__device__ __half g_hp  [(size_t)NPR * Hdim];
__device__ __half g_hu1 [(size_t)NU  * Hdim];
__device__ __half g_hp1 [(size_t)NPR * Hdim];
__device__ __half g_m_u [(size_t)NU  * Hdim];
__device__ __half g_m_p [(size_t)NPR * Hdim];
__device__ __half g_ng_p[(size_t)NPR * Hdim];
__device__ __half g_ng_u[(size_t)NU  * Hdim];

__device__ __half g_w_l1up_pre [Hdim * Hdim];
__device__ __half g_w_l1up_nb  [Hdim * Hdim];
__device__ __half g_w_l1up_self[Hdim * Hdim];
__device__ __half g_w_l1pu_pre [Hdim * Hdim];
__device__ __half g_w_l1pu_nb  [Hdim * Hdim];
__device__ __half g_w_l1pu_self[Hdim * Hdim];
__device__ __half g_w_l2up_pre [Hdim * Hdim];
__device__ __half g_w_l2up_nb  [Hdim * OUTD];
__device__ __half g_w_l2up_self[Hdim * OUTD];
__device__ __half g_w_l2pu_pre [Hdim * Hdim];
__device__ __half g_w_l2pu_nb  [Hdim * OUTD];
__device__ __half g_w_l2pu_self[Hdim * OUTD];

__device__ int g_eu_cnt[NPR];
__device__ int g_eu_off[NPR + 1];
__device__ int g_eu_cur[NPR];
__device__ int g_eu_adj[NE];

__device__ int g_ep_cnt[NU];
__device__ int g_ep_off[NU + 1];
__device__ int g_ep_cur[NU];
__device__ int g_ep_adj[NE];

// ---- streams/events created at static init ----
enum { EV_FORK = 0, EV_HP, EV_HU, EV_HP1, EV_HU1, EV_HU2, EV_HP2, EV_NEG, EV_COUNT };
static cudaStream_t g_s1;
static cudaEvent_t  g_ev[EV_COUNT];
struct InitStreams {
    InitStreams() {
        cudaStreamCreateWithFlags(&g_s1, cudaStreamNonBlocking);
        for (int i = 0; i < EV_COUNT; i++)
            cudaEventCreateWithFlags(&g_ev[i], cudaEventDisableTiming);
    }
};
static InitStreams g_init_streams;

// ------------------------- helpers -----------------------------------------
__device__ __forceinline__ uint32_t pack_h2(float x, float y) {
    __half2 h = __floats2half2_rn(x, y);
    return *reinterpret_cast<uint32_t*>(&h);
}

struct CvtBatch {
    const float* src[7];
    __half*      dst[7];
    int          n4[7];
};
__global__ void cvt_batch_k(CvtBatch b) {
    int y = blockIdx.y;
    int i = blockIdx.x * blockDim.x + threadIdx.x;
    if (i < b.n4[y]) {
        float4 v = reinterpret_cast<const float4*>(b.src[y])[i];
        uint32_t* d = reinterpret_cast<uint32_t*>(b.dst[y] + (size_t)i * 4);
        d[0] = pack_h2(v.x, v.y);
        d[1] = pack_h2(v.z, v.w);
    }
}

// ------------------------- CSR build ---------------------------------------
__global__ void zero_i_k(int* __restrict__ p, int n) {
    int i = blockIdx.x * blockDim.x + threadIdx.x;
    if (i < n) p[i] = 0;
}

__global__ void count_k(const int* __restrict__ dst, int* __restrict__ cnt, int n) {
    int i = blockIdx.x * blockDim.x + threadIdx.x;
    if (i < n) atomicAdd(&cnt[dst[i]], 1);
}

__global__ void scan_k(const int* __restrict__ cnt, int n,
                       int* __restrict__ off, int* __restrict__ cur) {
    __shared__ int sh[1024];
    const int tid = threadIdx.x;
    const int CH = (n + 1023) >> 10;
    const int s = tid * CH;
    const int e = min(s + CH, n);

    int local = 0;
    for (int i = s; i < e; i++) local += cnt[i];
    sh[tid] = local;
    __syncthreads();

    #pragma unroll
    for (int d = 1; d < 1024; d <<= 1) {
        int t = (tid >= d) ? sh[tid - d] : 0;
        __syncthreads();
        sh[tid] += t;
        __syncthreads();
    }
    int excl = sh[tid] - local;
    int total = sh[1023];

    int run = excl;
    for (int i = s; i < e; i++) {
        off[i] = run;
        cur[i] = run;
        run += cnt[i];
    }
    if (tid == 0) off[n] = total;
}

__global__ void scatter_k(const int* __restrict__ src, const int* __restrict__ dst,
                          int* __restrict__ cur, int* __restrict__ adj, int n) {
    int i = blockIdx.x * blockDim.x + threadIdx.x;
    if (i < n) {
        int pos = atomicAdd(&cur[dst[i]], 1);
        adj[pos] = src[i];
    }
}

// ------------------------- shared mma helpers -------------------------------
__device__ __forceinline__ void mma_f16(float c[4], uint32_t a0, uint32_t a1,
                                        uint32_t a2, uint32_t a3,
                                        uint32_t b0, uint32_t b1) {
    asm volatile(
        "mma.sync.aligned.m16n8k16.row.col.f32.f16.f16.f32 "
        "{%0,%1,%2,%3}, {%4,%5,%6,%7}, {%8,%9}, {%0,%1,%2,%3};\n"
        : "+f"(c[0]), "+f"(c[1]), "+f"(c[2]), "+f"(c[3])
        : "r"(a0), "r"(a1), "r"(a2), "r"(a3), "r"(b0), "r"(b1));
}

__device__ __forceinline__ void ldsm_x4(uint32_t f[4], uint32_t saddr) {
    asm volatile("ldmatrix.sync.aligned.m8n8.x4.shared.b16 {%0,%1,%2,%3}, [%4];"
                 : "=r"(f[0]), "=r"(f[1]), "=r"(f[2]), "=r"(f[3]) : "r"(saddr));
}
__device__ __forceinline__ void ldsm_x4_t(uint32_t f[4], uint32_t saddr) {
    asm volatile("ldmatrix.sync.aligned.m8n8.x4.trans.shared.b16 {%0,%1,%2,%3}, [%4];"
                 : "=r"(f[0]), "=r"(f[1]), "=r"(f[2]), "=r"(f[3]) : "r"(saddr));
}

// ------------------------- FP16 tensor-core GEMM (128x128) -----------------
#define CK 32
#define CA_LDH 40
#define CB_LDH 136
#define CA_STG (128 * CA_LDH)
#define CB_STG (CK * CB_LDH)

#define HK 64
#define HA_LDH 72
#define HB_LDH 136
#define HA_STG (128 * HA_LDH)
#define HB_STG (HK * HB_LDH)
#define HNST 3
#define GEMM_SMEM_BYTES (HNST * (HA_STG + HB_STG) * 2)

template <bool BIAS, bool RELU, bool DUAL, bool OUTF16, bool CVT, bool NORM>
__global__ void __launch_bounds__(256, 2)
gemm_tc(const void* __restrict__ A0v, const void* __restrict__ B0v,
        const void* __restrict__ A1v, const void* __restrict__ B1v,
        const float* __restrict__ bias, void* __restrict__ Cv,
        int M, int N, int K) {
    extern __shared__ __half smh[];

    const int bm = blockIdx.y * 128;
    const int bn = blockIdx.x * 128;
    const int tid  = threadIdx.x;
    const int lane = tid & 31;
    const int warp = tid >> 5;
    const int g = lane >> 2;
    const int t = lane & 3;
    const int wm = (warp & 1) * 64;
    const int wn = (warp >> 1) * 32;

    const int a_row = lane & 15;
    const int a_colh = (lane >> 4) * 8;
    const int b_row = ((lane >> 3) & 1) * 8 + (lane & 7);
    const int b_colh = (lane >> 4) * 8;

    float acc[4][4][4];
    #pragma unroll
    for (int i = 0; i < 4; i++)
        #pragma unroll
        for (int j = 0; j < 4; j++)
            #pragma unroll
            for (int r = 0; r < 4; r++) acc[i][j][r] = 0.f;

    auto step_k16 = [&](const __half* Asb, const __half* Bsb, int ko, int alh, int blh) {
        const uint32_t a_base = (uint32_t)__cvta_generic_to_shared(
            Asb + (wm + a_row) * alh + ko + a_colh);
        uint32_t af[4][4];
        #pragma unroll
        for (int mt = 0; mt < 4; mt++)
            ldsm_x4(af[mt], a_base + (uint32_t)(mt * 16 * alh * 2));
        uint32_t bq[2][4];
        #pragma unroll
        for (int nb = 0; nb < 2; nb++) {
            uint32_t b_base = (uint32_t)__cvta_generic_to_shared(
                Bsb + (ko + b_row) * blh + wn + nb * 16 + b_colh);
            ldsm_x4_t(bq[nb], b_base);
        }
        #pragma unroll
        for (int mt = 0; mt < 4; mt++)
            #pragma unroll
            for (int nt = 0; nt < 4; nt++) {
                const int nb = nt >> 1, sub = (nt & 1) * 2;
                mma_f16(acc[mt][nt], af[mt][0], af[mt][1], af[mt][2], af[mt][3],
                        bq[nb][sub], bq[nb][sub + 1]);
            }
    };

    if constexpr (!CVT) {
        const int tps = K / HK;
        const int ntiles = (DUAL ? 2 : 1) * tps;
        auto issue = [&](int tix) {
            if (tix < ntiles) {
                const __half* A = (const __half*)A0v;
                const __half* B = (const __half*)B0v;
                int k0 = tix;
                if (DUAL && tix >= tps) { A = (const __half*)A1v; B = (const __half*)B1v; k0 -= tps; }
                k0 *= HK;
                __half* Asb = smh + (tix % HNST) * HA_STG;
                __half* Bsb = smh + HNST * HA_STG + (tix % HNST) * HB_STG;
                #pragma unroll
                for (int i = 0; i < 4; i++) {
                    int idx = tid + i * 256;
                    int r = idx >> 3;
                    int c = idx & 7;
                    int rr = (bm + r < M) ? (bm + r) : (M - 1);
                    int sz = (bm + r < M) ? 16 : 0;
                    const __half* src = A + (size_t)rr * K + k0 + c * 8;
                    uint32_t dst = (uint32_t)__cvta_generic_to_shared(Asb + r * HA_LDH + c * 8);
                    asm volatile("cp.async.cg.shared.global [%0], [%1], 16, %2;\n"
                                 :: "r"(dst), "l"(src), "r"(sz));
                }
                #pragma unroll
                for (int i = 0; i < 4; i++) {
                    int idx = tid + i * 256;
                    int r = idx >> 4;
                    int c = idx & 15;
                    const __half* src = B + (size_t)(k0 + r) * N + bn + c * 8;
                    uint32_t dst = (uint32_t)__cvta_generic_to_shared(Bsb + r * HB_LDH + c * 8);
                    asm volatile("cp.async.cg.shared.global [%0], [%1], 16;\n"
                                 :: "r"(dst), "l"(src));
                }
            }
            asm volatile("cp.async.commit_group;\n" ::: "memory");
        };

        issue(0);
        issue(1);
        for (int tix = 0; tix < ntiles; tix++) {
            asm volatile("cp.async.wait_group 1;\n" ::: "memory");
            __syncthreads();
            issue(tix + 2);
            const __half* Asb = smh + (tix % HNST) * HA_STG;
            const __half* Bsb = smh + HNST * HA_STG + (tix % HNST) * HB_STG;
            #pragma unroll
            for (int kk = 0; kk < 4; kk++)
                step_k16(Asb, Bsb, kk * 16, HA_LDH, HB_LDH);
        }
    } else {
        const int ntiles = K / CK;
        float4 ar[4], br[4];
        auto load_tile = [&](int tix) {
            const float* A = (const float*)A0v;
            const float* B = (const float*)B0v;
            int k0 = tix * CK;
            #pragma unroll
            for (int i = 0; i < 4; i++) {
                int idx = tid + i * 256;
                int r = idx >> 3;
                int c = idx & 7;
                ar[i] = make_float4(0.f, 0.f, 0.f, 0.f);
                if (bm + r < M)
                    ar[i] = *reinterpret_cast<const float4*>(A + (size_t)(bm + r) * K + k0 + c * 4);
            }
            #pragma unroll
            for (int i = 0; i < 4; i++) {
                int idx = tid + i * 256;
                int r = idx >> 5;
                int c = idx & 31;
                br[i] = *reinterpret_cast<const float4*>(B + (size_t)(k0 + r) * N + bn + c * 4);
            }
        };
        auto store_tile = [&](int buf) {
            __half* Asb = smh + buf * CA_STG;
            __half* Bsb = smh + 2 * CA_STG + buf * CB_STG;
            #pragma unroll
            for (int i = 0; i < 4; i++) {
                int idx = tid + i * 256;
                int r = idx >> 3;
                int c = idx & 7;
                uint32_t* p = reinterpret_cast<uint32_t*>(Asb + r * CA_LDH + c * 4);
                p[0] = pack_h2(ar[i].x, ar[i].y);
                p[1] = pack_h2(ar[i].z, ar[i].w);
            }
            #pragma unroll
            for (int i = 0; i < 4; i++) {
                int idx = tid + i * 256;
                int r = idx >> 5;
                int c = idx & 31;
                uint32_t* p = reinterpret_cast<uint32_t*>(Bsb + r * CB_LDH + c * 4);
                p[0] = pack_h2(br[i].x, br[i].y);
                p[1] = pack_h2(br[i].z, br[i].w);
            }
        };

        load_tile(0);
        store_tile(0);
        __syncthreads();
        for (int tix = 0; tix < ntiles; tix++) {
            const int buf = tix & 1;
            if (tix + 1 < ntiles) load_tile(tix + 1);
            const __half* Asb = smh + buf * CA_STG;
            const __half* Bsb = smh + 2 * CA_STG + buf * CB_STG;
            #pragma unroll
            for (int kk = 0; kk < 2; kk++)
                step_k16(Asb, Bsb, kk * 16, CA_LDH, CB_LDH);
            if (tix + 1 < ntiles) {
                store_tile(buf ^ 1);
                __syncthreads();
            }
        }
    }

    if constexpr (NORM) {
        __syncthreads();
        float* rowsum = reinterpret_cast<float*>(smh);   // [128][4]
        const int nw = warp >> 1;
        const int mh = warp & 1;

        float part[4][2];
        #pragma unroll
        for (int mt = 0; mt < 4; mt++) {
            part[mt][0] = 0.f; part[mt][1] = 0.f;
            #pragma unroll
            for (int nt = 0; nt < 4; nt++) {
                #pragma unroll
                for (int h = 0; h < 2; h++) {
                    float vx = fmaxf(acc[mt][nt][h * 2 + 0], 0.f);
                    float vy = fmaxf(acc[mt][nt][h * 2 + 1], 0.f);
                    part[mt][h] += vx * vx + vy * vy;
                }
            }
        }
        #pragma unroll
        for (int mt = 0; mt < 4; mt++)
            #pragma unroll
            for (int h = 0; h < 2; h++) {
                part[mt][h] += __shfl_xor_sync(0xFFFFFFFFu, part[mt][h], 1);
                part[mt][h] += __shfl_xor_sync(0xFFFFFFFFu, part[mt][h], 2);
            }
        if (t == 0) {
            #pragma unroll
            for (int mt = 0; mt < 4; mt++)
                #pragma unroll
                for (int h = 0; h < 2; h++) {
                    int row = mh * 64 + mt * 16 + h * 8 + g;
                    rowsum[row * 4 + nw] = part[mt][h];
                }
        }
        __syncthreads();

        float* C = (float*)Cv;
        #pragma unroll
        for (int mt = 0; mt < 4; mt++) {
            #pragma unroll
            for (int h = 0; h < 2; h++) {
                int lrow = mh * 64 + mt * 16 + h * 8 + g;
                int r = bm + lrow;
                if (r >= M) continue;
                float s = rowsum[lrow * 4 + 0] + rowsum[lrow * 4 + 1]
                        + rowsum[lrow * 4 + 2] + rowsum[lrow * 4 + 3];
                float inv = (s > 0.f) ? rsqrtf(s) : 1.f;
                #pragma unroll
                for (int nt = 0; nt < 4; nt++) {
                    int col = wn + nt * 8 + t * 2;
                    float vx = fmaxf(acc[mt][nt][h * 2 + 0], 0.f) * inv;
                    float vy = fmaxf(acc[mt][nt][h * 2 + 1], 0.f) * inv;
                    *reinterpret_cast<float2*>(C + (size_t)r * N + col) = make_float2(vx, vy);
                }
            }
        }
        return;
    }

    #pragma unroll
    for (int mt = 0; mt < 4; mt++) {
        int r0 = bm + wm + mt * 16 + g;
        #pragma unroll
        for (int nt = 0; nt < 4; nt++) {
            int col = bn + wn + nt * 8 + t * 2;
            float b0 = 0.f, b1 = 0.f;
            if (BIAS) { b0 = bias[col]; b1 = bias[col + 1]; }
            #pragma unroll
            for (int h = 0; h < 2; h++) {
                int r = r0 + h * 8;
                if (r >= M) continue;
                float vx = acc[mt][nt][h * 2 + 0] + b0;
                float vy = acc[mt][nt][h * 2 + 1] + b1;
                if (RELU) { vx = fmaxf(vx, 0.f); vy = fmaxf(vy, 0.f); }
                if (OUTF16) {
                    __half* C = (__half*)Cv;
                    *reinterpret_cast<uint32_t*>(C + (size_t)r * N + col) = pack_h2(vx, vy);
                } else {
                    float* C = (float*)Cv;
                    *reinterpret_cast<float2*>(C + (size_t)r * N + col) = make_float2(vx, vy);
                }
            }
        }
    }
}

// --------- 64x256 dual GEMM + fused relu + row-L2-norm, fp16 out -----------
// 8 warps 1m x 8n; every warp owns all 64 rows. BK=32, 4-stage cp.async.
#define G64_K 32
#define G64_A_LDH 40                  // 80B row stride
#define G64_B_LDH 264                 // 528B row stride
#define G64_A_STG (64 * G64_A_LDH)
#define G64_B_STG (G64_K * G64_B_LDH)
#define G64_NST 4
#define GEMM64_SMEM_BYTES (G64_NST * (G64_A_STG + G64_B_STG) * 2)  // ~86 KB

__global__ void __launch_bounds__(256, 2)
gemm64_norm_tc(const __half* __restrict__ A0, const __half* __restrict__ B0,
               const __half* __restrict__ A1, const __half* __restrict__ B1,
               __half* __restrict__ C, int M) {
    extern __shared__ __half smh[];
    constexpr int N = 256, K = 256;
    const int tps = K / G64_K;          // 8
    const int ntiles = 2 * tps;         // 16

    const int bm = blockIdx.x * 64;
    const int tid  = threadIdx.x;
    const int lane = tid & 31;
    const int warp = tid >> 5;
    const int g = lane >> 2;
    const int t = lane & 3;
    const int wn = warp * 32;

    const int a_row = lane & 15;
    const int a_colh = (lane >> 4) * 8;
    const int b_row = ((lane >> 3) & 1) * 8 + (lane & 7);
    const int b_colh = (lane >> 4) * 8;

    float acc[4][4][4];
    #pragma unroll
    for (int i = 0; i < 4; i++)
        #pragma unroll
        for (int j = 0; j < 4; j++)
            #pragma unroll
            for (int r = 0; r < 4; r++) acc[i][j][r] = 0.f;

    auto issue = [&](int tix) {
        if (tix < ntiles) {
            const __half* A = A0;
            const __half* B = B0;
            int k0 = tix;
            if (tix >= tps) { A = A1; B = B1; k0 -= tps; }
            k0 *= G64_K;
            __half* Asb = smh + (tix % G64_NST) * G64_A_STG;
            __half* Bsb = smh + G64_NST * G64_A_STG + (tix % G64_NST) * G64_B_STG;
            // A: 64 rows x 4 chunks = 256 chunks -> 1 per thread
            {
                int r = tid >> 2;
                int c = tid & 3;
                int rr = (bm + r < M) ? (bm + r) : (M - 1);
                int sz = (bm + r < M) ? 16 : 0;
                const __half* src = A + (size_t)rr * K + k0 + c * 8;
                uint32_t dst = (uint32_t)__cvta_generic_to_shared(Asb + r * G64_A_LDH + c * 8);
                asm volatile("cp.async.cg.shared.global [%0], [%1], 16, %2;\n"
                             :: "r"(dst), "l"(src), "r"(sz));
            }
            // B: 32 k-rows x 32 chunks = 1024 chunks -> 4 per thread
            #pragma unroll
            for (int i = 0; i < 4; i++) {
                int idx = tid + i * 256;
                int r = idx >> 5;
                int c = idx & 31;
                const __half* src = B + (size_t)(k0 + r) * N + c * 8;
                uint32_t dst = (uint32_t)__cvta_generic_to_shared(Bsb + r * G64_B_LDH + c * 8);
                asm volatile("cp.async.cg.shared.global [%0], [%1], 16;\n"
                             :: "r"(dst), "l"(src));
            }
        }
        asm volatile("cp.async.commit_group;\n" ::: "memory");
    };

    issue(0);
    issue(1);
    issue(2);
    for (int tix = 0; tix < ntiles; tix++) {
        asm volatile("cp.async.wait_group 2;\n" ::: "memory");
        __syncthreads();
        issue(tix + 3);
        const __half* Asb = smh + (tix % G64_NST) * G64_A_STG;
        const __half* Bsb = smh + G64_NST * G64_A_STG + (tix % G64_NST) * G64_B_STG;
        #pragma unroll
        for (int kk = 0; kk < 2; kk++) {
            const int ko = kk * 16;
            const uint32_t a_base = (uint32_t)__cvta_generic_to_shared(
                Asb + a_row * G64_A_LDH + ko + a_colh);
            uint32_t af[4][4];
            #pragma unroll
            for (int mt = 0; mt < 4; mt++)
                ldsm_x4(af[mt], a_base + (uint32_t)(mt * 16 * G64_A_LDH * 2));
            uint32_t bq[2][4];
            #pragma unroll
            for (int nb = 0; nb < 2; nb++) {
                uint32_t b_base = (uint32_t)__cvta_generic_to_shared(
                    Bsb + (ko + b_row) * G64_B_LDH + wn + nb * 16 + b_colh);
                ldsm_x4_t(bq[nb], b_base);
            }
            #pragma unroll
            for (int mt = 0; mt < 4; mt++)
                #pragma unroll
                for (int nt = 0; nt < 4; nt++) {
                    const int nb = nt >> 1, sub = (nt & 1) * 2;
                    mma_f16(acc[mt][nt], af[mt][0], af[mt][1], af[mt][2], af[mt][3],
                            bq[nb][sub], bq[nb][sub + 1]);
                }
        }
    }

    // fused relu + row-L2-norm; all warps share the same 64 rows.
    __syncthreads();
    float* rowsum = reinterpret_cast<float*>(smh);   // [64][8]

    float part[4][2];
    #pragma unroll
    for (int mt = 0; mt < 4; mt++) {
        part[mt][0] = 0.f; part[mt][1] = 0.f;
        #pragma unroll
        for (int nt = 0; nt < 4; nt++) {
            #pragma unroll
            for (int h = 0; h < 2; h++) {
                float vx = fmaxf(acc[mt][nt][h * 2 + 0], 0.f);
                float vy = fmaxf(acc[mt][nt][h * 2 + 1], 0.f);
                part[mt][h] += vx * vx + vy * vy;
            }
        }
    }
    #pragma unroll
    for (int mt = 0; mt < 4; mt++)
        #pragma unroll
        for (int h = 0; h < 2; h++) {
            part[mt][h] += __shfl_xor_sync(0xFFFFFFFFu, part[mt][h], 1);
            part[mt][h] += __shfl_xor_sync(0xFFFFFFFFu, part[mt][h], 2);
        }
    if (t == 0) {
        #pragma unroll
        for (int mt = 0; mt < 4; mt++)
            #pragma unroll
            for (int h = 0; h < 2; h++) {
                int row = mt * 16 + h * 8 + g;
                rowsum[row * 8 + warp] = part[mt][h];
            }
    }
    __syncthreads();

    #pragma unroll
    for (int mt = 0; mt < 4; mt++) {
        #pragma unroll
        for (int h = 0; h < 2; h++) {
            int lrow = mt * 16 + h * 8 + g;
            int r = bm + lrow;
            if (r >= M) continue;
            float s = 0.f;
            #pragma unroll
            for (int wq = 0; wq < 8; wq++) s += rowsum[lrow * 8 + wq];
            float inv = (s > 0.f) ? rsqrtf(s) : 1.f;
            #pragma unroll
            for (int nt = 0; nt < 4; nt++) {
                int col = wn + nt * 8 + t * 2;
                float vx = fmaxf(acc[mt][nt][h * 2 + 0], 0.f) * inv;
                float vy = fmaxf(acc[mt][nt][h * 2 + 1], 0.f) * inv;
                *reinterpret_cast<uint32_t*>(C + (size_t)r * N + col) = pack_h2(vx, vy);
            }
        }
    }
}

// ------------------------- mean aggregation (fp16 in, fp16 out) ------------
__global__ void agg_mean_h_k(const __half* __restrict__ feat,
                             const int* __restrict__ off, const int* __restrict__ adj,
                             __half* __restrict__ out, int n_dst) {
    int w    = (blockIdx.x * blockDim.x + threadIdx.x) >> 5;
    int lane = threadIdx.x & 31;
    if (w >= n_dst) return;
    int s = off[w], e = off[w + 1];
    float acc[8] = {};
    const size_t loff = (size_t)lane * 8;

    auto accum = [&](uint4 v) {
        const uint32_t u[4] = {v.x, v.y, v.z, v.w};
        #pragma unroll
        for (int j = 0; j < 4; j++) {
            float2 f = __half22float2(*reinterpret_cast<const __half2*>(&u[j]));
            acc[j * 2 + 0] += f.x;
            acc[j * 2 + 1] += f.y;
        }
    };

    int i = s;
    for (; i + 1 < e; i += 2) {
        int s0 = adj[i], s1 = adj[i + 1];
        uint4 v0 = *reinterpret_cast<const uint4*>(feat + (size_t)s0 * Hdim + loff);
        uint4 v1 = *reinterpret_cast<const uint4*>(feat + (size_t)s1 * Hdim + loff);
        accum(v0);
        accum(v1);
    }
    if (i < e) {
        accum(*reinterpret_cast<const uint4*>(feat + (size_t)adj[i] * Hdim + loff));
    }

    float inv = 1.f / fmaxf((float)(e - s), 1.f);
    uint4 o;
    uint32_t* ow = reinterpret_cast<uint32_t*>(&o);
    #pragma unroll
    for (int j = 0; j < 4; j++)
        ow[j] = pack_h2(acc[j * 2] * inv, acc[j * 2 + 1] * inv);
    *reinterpret_cast<uint4*>(out + (size_t)w * Hdim + loff) = o;
}

// ------------------------- pair cosine dots --------------------------------
__global__ void pair_dot_k(const float* __restrict__ xu, const float* __restrict__ xp,
                           const int* __restrict__ iu, const int* __restrict__ ip,
                           float* __restrict__ outv, int n) {
    int w    = (blockIdx.x * blockDim.x + threadIdx.x) >> 5;
    int lane = threadIdx.x & 31;
    if (w >= n) return;
    int u = iu[w], p = ip[w];
    float4 a = reinterpret_cast<const float4*>(xu + (size_t)u * OUTD)[lane];
    float4 b = reinterpret_cast<const float4*>(xp + (size_t)p * OUTD)[lane];
    float s = a.x * b.x + a.y * b.y + a.z * b.z + a.w * b.w;
    #pragma unroll
    for (int o = 16; o; o >>= 1) s += __shfl_xor_sync(0xFFFFFFFFu, s, o);
    if (lane == 0) outv[w] = s;
}

// ------------------------- launch ------------------------------------------
static inline int cdiv(int a, int b) { return (a + b - 1) / b; }

extern "C" void kernel_launch(void* const* d_in, const int* in_sizes, int n_in,
                              void* d_out, int out_size) {
    const float* user_x = (const float*)d_in[0];
    const float* prod_x = (const float*)d_in[1];
    const float* W_ue   = (const float*)d_in[2];
    const float* b_ue   = (const float*)d_in[3];
    const float* W_pe   = (const float*)d_in[4];
    const float* b_pe   = (const float*)d_in[5];
    const float* l1_up_pre  = (const float*)d_in[6];
    const float* l1_up_nb   = (const float*)d_in[7];
    const float* l1_up_self = (const float*)d_in[8];
    const float* l1_pu_pre  = (const float*)d_in[9];
    const float* l1_pu_nb   = (const float*)d_in[10];
    const float* l1_pu_self = (const float*)d_in[11];
    const float* l2_up_pre  = (const float*)d_in[12];
    const float* l2_up_nb   = (const float*)d_in[13];
    const float* l2_up_self = (const float*)d_in[14];
    const float* l2_pu_pre  = (const float*)d_in[15];
    const float* l2_pu_nb   = (const float*)d_in[16];
    const float* l2_pu_self = (const float*)d_in[17];
    const int* eu_src = (const int*)d_in[18];
    const int* eu_dst = (const int*)d_in[19];
    const int* ep_src = (const int*)d_in[20];
    const int* ep_dst = (const int*)d_in[21];
    const int* pos_u  = (const int*)d_in[22];
    const int* pos_p  = (const int*)d_in[23];
    const int* neg_u  = (const int*)d_in[24];
    const int* neg_p  = (const int*)d_in[25];

    __half *hu, *hp, *hu1, *hp1, *m_u, *m_p, *ng_p, *ng_u;
    __half *w1up_pre, *w1up_nb, *w1up_self, *w1pu_pre, *w1pu_nb, *w1pu_self;
    __half *w2up_pre, *w2up_nb, *w2up_self, *w2pu_pre, *w2pu_nb, *w2pu_self;
    int *eu_cnt, *eu_off, *eu_cur, *eu_adj;
    int *ep_cnt, *ep_off, *ep_cur, *ep_adj;
    cudaGetSymbolAddress((void**)&hu,   g_hu);
    cudaGetSymbolAddress((void**)&hp,   g_hp);
    cudaGetSymbolAddress((void**)&hu1,  g_hu1);
    cudaGetSymbolAddress((void**)&hp1,  g_hp1);
    cudaGetSymbolAddress((void**)&m_u,  g_m_u);
    cudaGetSymbolAddress((void**)&m_p,  g_m_p);
    cudaGetSymbolAddress((void**)&ng_p, g_ng_p);
    cudaGetSymbolAddress((void**)&ng_u, g_ng_u);
    cudaGetSymbolAddress((void**)&w1up_pre,  g_w_l1up_pre);
    cudaGetSymbolAddress((void**)&w1up_nb,   g_w_l1up_nb);
    cudaGetSymbolAddress((void**)&w1up_self, g_w_l1up_self);
    cudaGetSymbolAddress((void**)&w1pu_pre,  g_w_l1pu_pre);
    cudaGetSymbolAddress((void**)&w1pu_nb,   g_w_l1pu_nb);
    cudaGetSymbolAddress((void**)&w1pu_self, g_w_l1pu_self);
    cudaGetSymbolAddress((void**)&w2up_pre,  g_w_l2up_pre);
    cudaGetSymbolAddress((void**)&w2up_nb,   g_w_l2up_nb);
    cudaGetSymbolAddress((void**)&w2up_self, g_w_l2up_self);
    cudaGetSymbolAddress((void**)&w2pu_pre,  g_w_l2pu_pre);
    cudaGetSymbolAddress((void**)&w2pu_nb,   g_w_l2pu_nb);
    cudaGetSymbolAddress((void**)&w2pu_self, g_w_l2pu_self);
    cudaGetSymbolAddress((void**)&eu_cnt, g_eu_cnt);
    cudaGetSymbolAddress((void**)&eu_off, g_eu_off);
    cudaGetSymbolAddress((void**)&eu_cur, g_eu_cur);
    cudaGetSymbolAddress((void**)&eu_adj, g_eu_adj);
    cudaGetSymbolAddress((void**)&ep_cnt, g_ep_cnt);
    cudaGetSymbolAddress((void**)&ep_off, g_ep_off);
    cudaGetSymbolAddress((void**)&ep_cur, g_ep_cur);
    cudaGetSymbolAddress((void**)&ep_adj, g_ep_adj);

    cudaFuncSetAttribute(gemm_tc<true,  false, false, true,  true,  false>,
                         cudaFuncAttributeMaxDynamicSharedMemorySize, GEMM_SMEM_BYTES);
    cudaFuncSetAttribute(gemm_tc<false, true,  false, true,  false, false>,
                         cudaFuncAttributeMaxDynamicSharedMemorySize, GEMM_SMEM_BYTES);
    cudaFuncSetAttribute(gemm_tc<false, false, true,  false, false, true>,
                         cudaFuncAttributeMaxDynamicSharedMemorySize, GEMM_SMEM_BYTES);
    cudaFuncSetAttribute(gemm64_norm_tc,
                         cudaFuncAttributeMaxDynamicSharedMemorySize, GEMM64_SMEM_BYTES);

    float* out = (float*)d_out;
    float* hu2 = out;
    float* hp2 = out + (size_t)NU * OUTD;
    float* pos = hp2 + (size_t)NPR * OUTD;
    float* neg = pos + NPAIR;

    cudaStream_t s0 = 0;
    cudaStream_t s1 = g_s1;

    const int GU = cdiv(NU, 128), GP = cdiv(NPR, 128);
    const int SMB = GEMM_SMEM_BYTES;
    const int HH4 = Hdim * Hdim / 4, HO4 = Hdim * OUTD / 4;

    // ---- fork ----
    cudaEventRecord(g_ev[EV_FORK], s0);
    cudaStreamWaitEvent(s1, g_ev[EV_FORK], 0);

    // ---- fused weight fp16 conversion: one launch per stream ----
    {
        CvtBatch b0;
        b0.src[0] = l1_up_pre;  b0.dst[0] = w1up_pre;  b0.n4[0] = HH4;
        b0.src[1] = l1_up_nb;   b0.dst[1] = w1up_nb;   b0.n4[1] = HH4;
        b0.src[2] = l1_up_self; b0.dst[2] = w1up_self; b0.n4[2] = HH4;
        b0.src[3] = l2_up_pre;  b0.dst[3] = w2up_pre;  b0.n4[3] = HH4;
        b0.src[4] = l2_up_nb;   b0.dst[4] = w2up_nb;   b0.n4[4] = HO4;
        b0.src[5] = l2_up_self; b0.dst[5] = w2up_self; b0.n4[5] = HO4;
        b0.src[6] = l2_up_self; b0.dst[6] = w2up_self; b0.n4[6] = 0;
        cvt_batch_k<<<dim3(cdiv(HH4, 256), 7), 256, 0, s0>>>(b0);

        CvtBatch b1;
        b1.src[0] = l1_pu_pre;  b1.dst[0] = w1pu_pre;  b1.n4[0] = HH4;
        b1.src[1] = l1_pu_nb;   b1.dst[1] = w1pu_nb;   b1.n4[1] = HH4;
        b1.src[2] = l1_pu_self; b1.dst[2] = w1pu_self; b1.n4[2] = HH4;
        b1.src[3] = l2_pu_pre;  b1.dst[3] = w2pu_pre;  b1.n4[3] = HH4;
        b1.src[4] = l2_pu_nb;   b1.dst[4] = w2pu_nb;   b1.n4[4] = HO4;
        b1.src[5] = l2_pu_self; b1.dst[5] = w2pu_self; b1.n4[5] = HO4;
        b1.src[6] = l2_pu_self; b1.dst[6] = w2pu_self; b1.n4[6] = 0;
        cvt_batch_k<<<dim3(cdiv(HH4, 256), 7), 256, 0, s1>>>(b1);
    }

    // ---- projections (fp32 in, CVT path; fp16 out) ----
    gemm_tc<true, false, false, true, true, false><<<dim3(2, GU), 256, SMB, s0>>>(user_x, W_ue, nullptr, nullptr, b_ue, hu, NU, Hdim, DU);
    cudaEventRecord(g_ev[EV_HU], s0);
    gemm_tc<true, false, false, true, true, false><<<dim3(2, GP), 256, SMB, s1>>>(prod_x, W_pe, nullptr, nullptr, b_pe, hp, NPR, Hdim, DU);
    cudaEventRecord(g_ev[EV_HP], s1);

    // ---- CSR builds (s0: eu, s1: ep) ----
    zero_i_k<<<cdiv(NPR, 256), 256, 0, s0>>>(eu_cnt, NPR);
    count_k<<<cdiv(NE, 256), 256, 0, s0>>>(eu_dst, eu_cnt, NE);
    scan_k<<<1, 1024, 0, s0>>>(eu_cnt, NPR, eu_off, eu_cur);
    scatter_k<<<cdiv(NE, 256), 256, 0, s0>>>(eu_src, eu_dst, eu_cur, eu_adj, NE);

    zero_i_k<<<cdiv(NU, 256), 256, 0, s1>>>(ep_cnt, NU);
    count_k<<<cdiv(NE, 256), 256, 0, s1>>>(ep_dst, ep_cnt, NE);
    scan_k<<<1, 1024, 0, s1>>>(ep_cnt, NU, ep_off, ep_cur);
    scatter_k<<<cdiv(NE, 256), 256, 0, s1>>>(ep_src, ep_dst, ep_cur, ep_adj, NE);

    // ---- layer 1, up-chain on s0 (dst = products) ----
    gemm_tc<false, true, false, true, false, false><<<dim3(2, GU), 256, SMB, s0>>>(hu, w1up_pre, nullptr, nullptr, nullptr, m_u, NU, Hdim, Hdim);
    agg_mean_h_k<<<cdiv(NPR * 32, 256), 256, 0, s0>>>(m_u, eu_off, eu_adj, ng_p, NPR);
    cudaStreamWaitEvent(s0, g_ev[EV_HP], 0);
    gemm64_norm_tc<<<cdiv(NPR, 64), 256, GEMM64_SMEM_BYTES, s0>>>(hp, w1up_self, ng_p, w1up_nb, hp1, NPR);
    cudaEventRecord(g_ev[EV_HP1], s0);

    // ---- layer 1, pu-chain on s1 (dst = users) ----
    gemm_tc<false, true, false, true, false, false><<<dim3(2, GP), 256, SMB, s1>>>(hp, w1pu_pre, nullptr, nullptr, nullptr, m_p, NPR, Hdim, Hdim);
    agg_mean_h_k<<<cdiv(NU * 32, 256), 256, 0, s1>>>(m_p, ep_off, ep_adj, ng_u, NU);
    cudaStreamWaitEvent(s1, g_ev[EV_HU], 0);
    gemm64_norm_tc<<<cdiv(NU, 64), 256, GEMM64_SMEM_BYTES, s1>>>(hu, w1pu_self, ng_u, w1pu_nb, hu1, NU);
    cudaEventRecord(g_ev[EV_HU1], s1);

    // ---- layer 2, up-chain on s0 (fused norm epilogue, fp32 out) ----
    cudaStreamWaitEvent(s0, g_ev[EV_HU1], 0);
    gemm_tc<false, true, false, true, false, false><<<dim3(2, GU), 256, SMB, s0>>>(hu1, w2up_pre, nullptr, nullptr, nullptr, m_u, NU, Hdim, Hdim);
    agg_mean_h_k<<<cdiv(NPR * 32, 256), 256, 0, s0>>>(m_u, eu_off, eu_adj, ng_p, NPR);
    gemm_tc<false, false, true, false, false, true><<<dim3(1, GP), 256, SMB, s0>>>(hp1, w2up_self, ng_p, w2up_nb, nullptr, hp2, NPR, OUTD, Hdim);
    cudaEventRecord(g_ev[EV_HP2], s0);

    // ---- layer 2, pu-chain on s1 (fused norm epilogue, fp32 out) ----
    cudaStreamWaitEvent(s1, g_ev[EV_HP1], 0);
    gemm_tc<false, true, false, true, false, false><<<dim3(2, GP), 256, SMB, s1>>>(hp1, w2pu_pre, nullptr, nullptr, nullptr, m_p, NPR, Hdim, Hdim);
    agg_mean_h_k<<<cdiv(NU * 32, 256), 256, 0, s1>>>(m_p, ep_off, ep_adj, ng_u, NU);
    gemm_tc<false, false, true, false, false, true><<<dim3(1, GU), 256, SMB, s1>>>(hu1, w2pu_self, ng_u, w2pu_nb, nullptr, hu2, NU, OUTD, Hdim);
    cudaEventRecord(g_ev[EV_HU2], s1);

    // ---- pair dots split across streams ----
    cudaStreamWaitEvent(s0, g_ev[EV_HU2], 0);
    pair_dot_k<<<cdiv(NPAIR * 32, 256), 256, 0, s0>>>(hu2, hp2, pos_u, pos_p, pos, NPAIR);
    cudaStreamWaitEvent(s1, g_ev[EV_HP2], 0);
    pair_dot_k<<<cdiv(NPAIR * 32, 256), 256, 0, s1>>>(hu2, hp2, neg_u, neg_p, neg, NPAIR);
    cudaEventRecord(g_ev[EV_NEG], s1);
    cudaStreamWaitEvent(s0, g_ev[EV_NEG], 0);
}